// round 12
// baseline (speedup 1.0000x reference)
#include <cuda_runtime.h>

#define B_    64
#define D_    512
#define N_    1200
#define K_    64
#define NT_   5            // number of 256-wide n tiles
#define NTILE 256
#define NPAD  1280         // NT_*NTILE
#define EPSF  1e-12f

// Scratch (static __device__ arrays per harness rules)
__device__ float g_a[B_ * K_ * NPAD];        // a' = softmax * invnorm(x), zero-padded in n
__device__ float g_asum_part[B_ * NT_ * K_]; // per-tile partial sums of a (unscaled)

typedef unsigned long long u64;

static __device__ __forceinline__ u64 pk(float lo, float hi){
    union { u64 u; float2 f; } t; t.f = make_float2(lo, hi); return t.u;
}
static __device__ __forceinline__ float2 upk(u64 v){
    union { u64 u; float2 f; } t; t.u = v; return t.f;
}
static __device__ __forceinline__ void fma2(u64 &acc, u64 a, u64 b){
    // packed fp32x2 FMA: acc.lo += a.lo*b.lo ; acc.hi += a.hi*b.hi
    asm("fma.rn.f32x2 %0, %1, %2, %0;" : "+l"(acc) : "l"(a), "l"(b));
}

// ---------------------------------------------------------------------------
// KA: per (batch, 256-pixel tile): logits GEMM (64k x 256n, D=512),
//     fused sumsq->invnorm, softmax over K, write a' and asum partials.
//     512 threads, thread tile 8k x 4n -> 16 u64 accs (32 regs), 16 warps,
//     no spills (R9 lesson: never buy occupancy with spills).
//     LDG prefetch-to-register hides staging latency behind compute.
// ---------------------------------------------------------------------------
__global__ __launch_bounds__(512) void ka_logits(const float* __restrict__ x,
                                                 const float* __restrict__ w)
{
    __shared__ __align__(16) float SM[4096 + 2112];
    float*     xs   = SM;                                   // 16 dd x 256 floats
    u64*       ws   = reinterpret_cast<u64*>(SM + 4096);    // 16 dd x 66 dup-pairs
    const u64* xs64 = reinterpret_cast<const u64*>(SM);     // rows of 128 u64

    const int tid  = threadIdx.x;
    const int tile = blockIdx.x;
    const int b    = blockIdx.y;
    const int n0   = tile * NTILE;
    const int wid  = tid >> 5;
    const int ng   = tid & 31;
    const int kg   = wid & 7;      // k-group: k = kg*8 + i
    const int nh   = wid >> 3;     // n-half: columns nh*128 .. nh*128+127

    u64 acc[8][2];
    #pragma unroll
    for (int i = 0; i < 8; ++i){ acc[i][0] = 0ULL; acc[i][1] = 0ULL; }

    float4 s4 = make_float4(0.f, 0.f, 0.f, 0.f);
    const float* xb = x + (size_t)b * D_ * N_;
    const int n4  = tid & 63;      // x stager: float4 column
    const int rr  = tid >> 6;      // x stager: row group (0..7), rows rr, rr+8
    const int wdd = tid & 15;      // w stager: dd
    const int wk  = tid >> 4;      // w stager: k and k+32

    const int  nc     = n0 + 4*n4;
    const bool nvalid = (nc < N_);

    // prefetch chunk 0
    float4 px[2]; float pw[2];
    #pragma unroll
    for (int it = 0; it < 2; ++it){
        px[it] = make_float4(0.f, 0.f, 0.f, 0.f);
        if (nvalid) px[it] = *reinterpret_cast<const float4*>(xb + (size_t)(rr + 8*it) * N_ + nc);
        pw[it] = w[((wk + 32*it) << 9) + wdd];
    }

    for (int c = 0; c < D_; c += 16){
        // store staged chunk (sync at loop bottom ordered prev compute before this)
        *reinterpret_cast<float4*>(xs + rr*256      + 4*n4) = px[0];
        *reinterpret_cast<float4*>(xs + (rr+8)*256  + 4*n4) = px[1];
        s4.x += px[0].x*px[0].x + px[1].x*px[1].x;
        s4.y += px[0].y*px[0].y + px[1].y*px[1].y;
        s4.z += px[0].z*px[0].z + px[1].z*px[1].z;
        s4.w += px[0].w*px[0].w + px[1].w*px[1].w;
        ws[wdd*66 + wk     ] = pk(pw[0], pw[0]);
        ws[wdd*66 + wk + 32] = pk(pw[1], pw[1]);
        __syncthreads();

        // prefetch next chunk (independent of smem; overlaps compute below)
        if (c + 16 < D_){
            #pragma unroll
            for (int it = 0; it < 2; ++it){
                px[it] = make_float4(0.f, 0.f, 0.f, 0.f);
                if (nvalid) px[it] = *reinterpret_cast<const float4*>(
                                        xb + (size_t)(c + 16 + rr + 8*it) * N_ + nc);
                pw[it] = w[((wk + 32*it) << 9) + c + 16 + wdd];
            }
        }

        #pragma unroll
        for (int dd = 0; dd < 16; ++dd){
            u64 xp0 = xs64[dd*128 + nh*64 + ng];
            u64 xp1 = xs64[dd*128 + nh*64 + ng + 32];
            const ulonglong2* wr = reinterpret_cast<const ulonglong2*>(ws) + dd*33 + kg*4;
            #pragma unroll
            for (int q = 0; q < 4; ++q){
                ulonglong2 wv = wr[q];   // warp-uniform -> broadcast LDS.128
                fma2(acc[2*q  ][0], wv.x, xp0);
                fma2(acc[2*q  ][1], wv.x, xp1);
                fma2(acc[2*q+1][0], wv.y, xp0);
                fma2(acc[2*q+1][1], wv.y, xp1);
            }
        }
        __syncthreads();
    }

    // ---- sumsq -> invnorm ----
    float4* red4 = reinterpret_cast<float4*>(SM);   // 512 float4 = floats [0,2048)
    float*  sinv = SM + 2048;                       // 256 floats [2048,2304)
    float*  red  = SM + 4096;                       // 2048 floats (ws region)

    red4[rr*64 + n4] = s4;
    __syncthreads();
    if (tid < 64){
        float sx = 0.f, sy = 0.f, sz = 0.f, sw = 0.f;
        #pragma unroll
        for (int r = 0; r < 8; ++r){
            float4 a0 = red4[r*64 + tid];
            sx += a0.x; sy += a0.y; sz += a0.z; sw += a0.w;
        }
        int nb = n0 + 4*tid;
        sinv[4*tid+0] = (nb+0 < N_) ? 1.f/fmaxf(sqrtf(sx), EPSF) : 0.f;
        sinv[4*tid+1] = (nb+1 < N_) ? 1.f/fmaxf(sqrtf(sy), EPSF) : 0.f;
        sinv[4*tid+2] = (nb+2 < N_) ? 1.f/fmaxf(sqrtf(sz), EPSF) : 0.f;
        sinv[4*tid+3] = (nb+3 < N_) ? 1.f/fmaxf(sqrtf(sw), EPSF) : 0.f;
    }
    __syncthreads();

    const int nlb = nh*128 + 2*ng;        // nl(p,e) = nlb + 64*p + e
    float inv[4];
    #pragma unroll
    for (int p = 0; p < 2; ++p){
        inv[2*p]   = sinv[nlb + 64*p];
        inv[2*p+1] = sinv[nlb + 64*p + 1];
    }

    // scale logits by invnorm
    #pragma unroll
    for (int i = 0; i < 8; ++i)
        #pragma unroll
        for (int p = 0; p < 2; ++p){
            float2 f = upk(acc[i][p]);
            acc[i][p] = pk(f.x * inv[2*p], f.y * inv[2*p+1]);
        }

    // ---- softmax over K=64 per pixel ----
    #pragma unroll
    for (int p = 0; p < 2; ++p){
        float m0 = -3.4e38f, m1 = -3.4e38f;
        #pragma unroll
        for (int i = 0; i < 8; ++i){
            float2 f = upk(acc[i][p]);
            m0 = fmaxf(m0, f.x); m1 = fmaxf(m1, f.y);
        }
        red[kg*256 + nlb + 64*p    ] = m0;
        red[kg*256 + nlb + 64*p + 1] = m1;
    }
    __syncthreads();
    float M[4];
    #pragma unroll
    for (int j = 0; j < 4; ++j){
        int nl = nlb + 64*(j >> 1) + (j & 1);
        float m = red[nl];
        #pragma unroll
        for (int g = 1; g < 8; ++g) m = fmaxf(m, red[g*256 + nl]);
        M[j] = m;
    }
    __syncthreads();

    float ss[4] = {0.f, 0.f, 0.f, 0.f};
    #pragma unroll
    for (int i = 0; i < 8; ++i)
        #pragma unroll
        for (int p = 0; p < 2; ++p){
            float2 f = upk(acc[i][p]);
            float e0 = __expf(f.x - M[2*p]);
            float e1 = __expf(f.y - M[2*p+1]);
            acc[i][p] = pk(e0, e1);
            ss[2*p] += e0; ss[2*p+1] += e1;
        }
    #pragma unroll
    for (int j = 0; j < 4; ++j)
        red[kg*256 + nlb + 64*(j >> 1) + (j & 1)] = ss[j];
    __syncthreads();
    float rS[4];
    #pragma unroll
    for (int j = 0; j < 4; ++j){
        int nl = nlb + 64*(j >> 1) + (j & 1);
        float s = red[nl];
        #pragma unroll
        for (int g = 1; g < 8; ++g) s += red[g*256 + nl];
        rS[j] = 1.f / s;
    }

    // ---- write a' = a * invnorm (0 in padding) + asum partials ----
    float* wsum = SM;                 // 128 floats; red4/sinv no longer needed
    float* ga = g_a + ((size_t)(b*K_) + kg*8) * NPAD;
    #pragma unroll
    for (int i = 0; i < 8; ++i){
        float asi = 0.f;
        #pragma unroll
        for (int p = 0; p < 2; ++p){
            int nl = nlb + 64*p;
            int n  = n0 + nl;
            float2 f = upk(acc[i][p]);
            float a0 = f.x * rS[2*p];
            float a1 = f.y * rS[2*p+1];
            if (n >= N_) { a0 = 0.f; a1 = 0.f; }   // n even, N_ even -> joint validity
            asi += a0 + a1;
            *reinterpret_cast<float2*>(ga + (size_t)i*NPAD + n) =
                make_float2(a0 * inv[2*p], a1 * inv[2*p+1]);
        }
        #pragma unroll
        for (int off = 16; off; off >>= 1) asi += __shfl_xor_sync(0xffffffffu, asi, off);
        if (ng == 0) wsum[wid*8 + i] = asi;        // warp's 128-n half partial
    }
    __syncthreads();
    if (tid < 64)   // k = tid; halves at wsum[k] (nh=0) and wsum[64+k] (nh=1)
        g_asum_part[(b*NT_ + tile)*K_ + tid] = wsum[tid] + wsum[64 + tid];
}

// ---------------------------------------------------------------------------
// KB: vlad_raw[b,k,d] = sum_n a'[b,k,n] * x[b,d,n]
//     CTA = (128-d tile, batch), 256 threads, thread tile 8k x 4d (32-reg acc).
//     a' duplicated in smem, read broadcast; LDG prefetch-to-register.
// ---------------------------------------------------------------------------
__global__ __launch_bounds__(256) void kb_vlad(const float* __restrict__ x,
                                               float* __restrict__ out)
{
    __shared__ __align__(16) float xsm[32*130];  // [nn][d], rows of 130 floats
    __shared__ __align__(16) u64   adu[32*66];   // [nn][k] duplicated pairs
    const u64* xs64 = reinterpret_cast<const u64*>(xsm);   // rows of 65 u64

    const int tid = threadIdx.x;
    const int d0  = blockIdx.x * 128;
    const int b   = blockIdx.y;
    const int kg  = tid >> 5;     // warp id = k-group: k = kg*8 + i
    const int dg  = tid & 31;     // lane: d-pairs 2*dg and 64+2*dg
    const int sl  = tid & 31;     // stager: nn
    const int sb  = tid >> 5;     // stager: k/d base

    u64 acc[8][2];
    #pragma unroll
    for (int i = 0; i < 8; ++i){ acc[i][0] = 0ULL; acc[i][1] = 0ULL; }

    const float* xb = x   + (size_t)b * D_ * N_;
    const float* ab = g_a + (size_t)b * K_ * NPAD;

    // prefetch chunk 0
    float ra[8], rx[16];
    #pragma unroll
    for (int it = 0; it < 8; ++it)
        ra[it] = ab[(size_t)(sb + 8*it)*NPAD + sl];
    #pragma unroll
    for (int it = 0; it < 16; ++it)
        rx[it] = (sl < N_) ? xb[(size_t)(d0 + sb + 8*it)*N_ + sl] : 0.f;

    for (int n0 = 0; n0 < NPAD; n0 += 32){
        #pragma unroll
        for (int it = 0; it < 8; ++it)
            adu[sl*66 + sb + 8*it] = pk(ra[it], ra[it]);
        #pragma unroll
        for (int it = 0; it < 16; ++it)
            xsm[sl*130 + sb + 8*it] = rx[it];
        __syncthreads();

        if (n0 + 32 < NPAD){
            int gn = n0 + 32 + sl;
            #pragma unroll
            for (int it = 0; it < 8; ++it)
                ra[it] = ab[(size_t)(sb + 8*it)*NPAD + gn];
            #pragma unroll
            for (int it = 0; it < 16; ++it)
                rx[it] = (gn < N_) ? xb[(size_t)(d0 + sb + 8*it)*N_ + gn] : 0.f;
        }

        #pragma unroll 8
        for (int nn = 0; nn < 32; ++nn){
            u64 xp0 = xs64[nn*65 + dg];
            u64 xp1 = xs64[nn*65 + 32 + dg];
            const ulonglong2* ar = reinterpret_cast<const ulonglong2*>(adu) + nn*33 + kg*4;
            #pragma unroll
            for (int q = 0; q < 4; ++q){
                ulonglong2 av = ar[q];   // warp-uniform -> broadcast
                fma2(acc[2*q  ][0], av.x, xp0);
                fma2(acc[2*q  ][1], av.x, xp1);
                fma2(acc[2*q+1][0], av.y, xp0);
                fma2(acc[2*q+1][1], av.y, xp1);
            }
        }
        __syncthreads();
    }

    float* ob = out + ((size_t)(b*K_) + kg*8) * D_ + d0;
    #pragma unroll
    for (int i = 0; i < 8; ++i)
        #pragma unroll
        for (int p = 0; p < 2; ++p){
            float2 f = upk(acc[i][p]);
            *reinterpret_cast<float2*>(ob + (size_t)i*D_ + 2*dg + 64*p) = f;
        }
}

// ---------------------------------------------------------------------------
// KC: per (k,b): asum from partials, centroid residual, intra-normalize row,
//     global L2 folded in (rows unit-norm -> global norm = sqrt(64) = 8).
// ---------------------------------------------------------------------------
__global__ __launch_bounds__(128) void kc_norm(float* __restrict__ out,
                                               const float* __restrict__ cent)
{
    __shared__ float sh[128];
    const int k = blockIdx.x, b = blockIdx.y;
    const int tid = threadIdx.x;

    float s = (tid < NT_) ? g_asum_part[(b*NT_ + tid)*K_ + k] : 0.f;
    sh[tid] = s; __syncthreads();
    for (int o = 64; o; o >>= 1){ if (tid < o) sh[tid] += sh[tid + o]; __syncthreads(); }
    float asum = sh[0];
    __syncthreads();

    float*       row  = out  + ((size_t)(b*K_ + k))*D_;
    const float* crow = cent + (size_t)k*D_;
    float v[4]; float sq = 0.f;
    #pragma unroll
    for (int j = 0; j < 4; ++j){
        int d = tid + 128*j;
        v[j] = row[d] - asum * crow[d];
        sq += v[j]*v[j];
    }
    sh[tid] = sq; __syncthreads();
    for (int o = 64; o; o >>= 1){ if (tid < o) sh[tid] += sh[tid + o]; __syncthreads(); }
    float inv = 0.125f / fmaxf(sqrtf(sh[0]), EPSF);
    #pragma unroll
    for (int j = 0; j < 4; ++j) row[tid + 128*j] = v[j] * inv;
}

// ---------------------------------------------------------------------------
extern "C" void kernel_launch(void* const* d_in, const int* in_sizes, int n_in,
                              void* d_out, int out_size)
{
    const float* x = (const float*)d_in[0];   // (B, D, H, W)
    const float* w = (const float*)d_in[1];   // (K, D)
    const float* c = (const float*)d_in[2];   // (K, D)
    float* out = (float*)d_out;               // (B, K*D)

    ka_logits<<<dim3(NT_, B_), 512>>>(x, w);
    kb_vlad  <<<dim3(D_/128, B_), 256>>>(x, out);
    kc_norm  <<<dim3(K_, B_), 128>>>(out, c);
}

// round 13
// speedup vs baseline: 1.1283x; 1.1283x over previous
#include <cuda_runtime.h>

#define B_    64
#define D_    512
#define N_    1200
#define K_    64
#define NT_   5
#define NTILE 256
#define NPAD  1280
#define EPSF  1e-12f

__device__ __align__(16) float g_a[B_ * K_ * NPAD];   // a' = softmax*invnorm, 0-padded
__device__ float g_asum_part[B_ * NT_ * K_];

typedef unsigned long long u64;

static __device__ __forceinline__ u64 pk(float lo, float hi){
    union { u64 u; float2 f; } t; t.f = make_float2(lo, hi); return t.u;
}
static __device__ __forceinline__ float2 upk(u64 v){
    union { u64 u; float2 f; } t; t.u = v; return t.f;
}
static __device__ __forceinline__ void fma2(u64 &acc, u64 a, u64 b){
    asm("fma.rn.f32x2 %0, %1, %2, %0;" : "+l"(acc) : "l"(a), "l"(b));
}

// ---------------------------------------------------------------------------
// KA: logits GEMM (64k x 256n, D=512) + fused invnorm + softmax.
//     k-paired accumulators: acc[j][e] = logits (k0+2j, k0+2j+1) for pixel e.
//     w PLAIN in smem (2 broadcast LDS.128 per dd), x LDS.128 + register dup.
//     6 L1 wavefronts per 32 fma-cycles (was 8 = saturated).
// ---------------------------------------------------------------------------
__global__ __launch_bounds__(512) void ka_logits(const float* __restrict__ x,
                                                 const float* __restrict__ w)
{
    __shared__ __align__(16) float SM[5184];
    float* xs = SM;            // 16 dd x 256 floats
    float* ws = SM + 4096;     // 16 dd x 68 floats (plain w, row 272 B)

    const int tid  = threadIdx.x;
    const int tile = blockIdx.x, b = blockIdx.y;
    const int n0   = tile * NTILE;
    const int wid  = tid >> 5, ng = tid & 31;
    const int kg   = wid & 7;          // k0 = kg*8
    const int nh   = wid >> 3;
    const int nb   = nh*128 + 4*ng;    // 4 pixels nb..nb+3

    u64 acc[4][4];
    #pragma unroll
    for (int j = 0; j < 4; ++j)
        #pragma unroll
        for (int e = 0; e < 4; ++e) acc[j][e] = 0ULL;

    float4 s4 = make_float4(0.f, 0.f, 0.f, 0.f);
    const float* xb = x + (size_t)b * D_ * N_;
    const int n4  = tid & 63;      // x stager column (float4)
    const int rr  = tid >> 6;      // x stager rows rr, rr+8
    const int wdd = tid & 15;      // w stager dd
    const int wk  = tid >> 4;      // w stager k, k+32
    const int nc  = n0 + 4*n4;
    const bool nvalid = (nc < N_);

    float4 px[2]; float pw0, pw1;
    #pragma unroll
    for (int it = 0; it < 2; ++it){
        px[it] = make_float4(0.f, 0.f, 0.f, 0.f);
        if (nvalid) px[it] = *reinterpret_cast<const float4*>(xb + (size_t)(rr + 8*it)*N_ + nc);
    }
    pw0 = w[ wk      * D_ + wdd];
    pw1 = w[(wk+32) * D_ + wdd];

    for (int c = 0; c < D_; c += 16){
        *reinterpret_cast<float4*>(xs + rr*256     + 4*n4) = px[0];
        *reinterpret_cast<float4*>(xs + (rr+8)*256 + 4*n4) = px[1];
        s4.x += px[0].x*px[0].x + px[1].x*px[1].x;
        s4.y += px[0].y*px[0].y + px[1].y*px[1].y;
        s4.z += px[0].z*px[0].z + px[1].z*px[1].z;
        s4.w += px[0].w*px[0].w + px[1].w*px[1].w;
        ws[wdd*68 + wk     ] = pw0;
        ws[wdd*68 + wk + 32] = pw1;
        __syncthreads();

        if (c + 16 < D_){
            #pragma unroll
            for (int it = 0; it < 2; ++it){
                px[it] = make_float4(0.f, 0.f, 0.f, 0.f);
                if (nvalid) px[it] = *reinterpret_cast<const float4*>(
                                        xb + (size_t)(c + 16 + rr + 8*it)*N_ + nc);
            }
            pw0 = w[ wk      * D_ + c + 16 + wdd];
            pw1 = w[(wk+32) * D_ + c + 16 + wdd];
        }

        // pipelined inner loop
        float4 xf = *reinterpret_cast<const float4*>(xs + nb);
        ulonglong2 wa = *reinterpret_cast<const ulonglong2*>(ws + kg*8);
        ulonglong2 wb = *reinterpret_cast<const ulonglong2*>(ws + kg*8 + 4);
        #pragma unroll
        for (int dd = 0; dd < 16; ++dd){
            float4 xn; ulonglong2 wan, wbn;
            if (dd < 15){
                xn  = *reinterpret_cast<const float4*>(xs + (dd+1)*256 + nb);
                wan = *reinterpret_cast<const ulonglong2*>(ws + (dd+1)*68 + kg*8);
                wbn = *reinterpret_cast<const ulonglong2*>(ws + (dd+1)*68 + kg*8 + 4);
            }
            u64 x0 = pk(xf.x, xf.x), x1 = pk(xf.y, xf.y);
            u64 x2 = pk(xf.z, xf.z), x3 = pk(xf.w, xf.w);
            fma2(acc[0][0], wa.x, x0); fma2(acc[0][1], wa.x, x1);
            fma2(acc[0][2], wa.x, x2); fma2(acc[0][3], wa.x, x3);
            fma2(acc[1][0], wa.y, x0); fma2(acc[1][1], wa.y, x1);
            fma2(acc[1][2], wa.y, x2); fma2(acc[1][3], wa.y, x3);
            fma2(acc[2][0], wb.x, x0); fma2(acc[2][1], wb.x, x1);
            fma2(acc[2][2], wb.x, x2); fma2(acc[2][3], wb.x, x3);
            fma2(acc[3][0], wb.y, x0); fma2(acc[3][1], wb.y, x1);
            fma2(acc[3][2], wb.y, x2); fma2(acc[3][3], wb.y, x3);
            if (dd < 15){ xf = xn; wa = wan; wb = wbn; }
        }
        __syncthreads();
    }

    // ---- sumsq -> invnorm ----
    float4* red4 = reinterpret_cast<float4*>(SM);   // floats [0,2048)
    float*  sinv = SM + 2048;                       // [2048,2304)
    float*  red  = SM + 2304;                       // [2304,4352)
    float*  wsum = SM + 4352;                       // [4352,4480)

    red4[rr*64 + n4] = s4;
    __syncthreads();
    if (tid < 64){
        float sx = 0.f, sy = 0.f, sz = 0.f, sw = 0.f;
        #pragma unroll
        for (int r = 0; r < 8; ++r){
            float4 a0 = red4[r*64 + tid];
            sx += a0.x; sy += a0.y; sz += a0.z; sw += a0.w;
        }
        int nbx = n0 + 4*tid;
        sinv[4*tid+0] = (nbx+0 < N_) ? 1.f/fmaxf(sqrtf(sx), EPSF) : 0.f;
        sinv[4*tid+1] = (nbx+1 < N_) ? 1.f/fmaxf(sqrtf(sy), EPSF) : 0.f;
        sinv[4*tid+2] = (nbx+2 < N_) ? 1.f/fmaxf(sqrtf(sz), EPSF) : 0.f;
        sinv[4*tid+3] = (nbx+3 < N_) ? 1.f/fmaxf(sqrtf(sw), EPSF) : 0.f;
    }
    __syncthreads();

    float ivv[4];
    {
        float4 iv4 = *reinterpret_cast<const float4*>(sinv + nb);
        ivv[0]=iv4.x; ivv[1]=iv4.y; ivv[2]=iv4.z; ivv[3]=iv4.w;
    }
    // scale logits by invnorm
    #pragma unroll
    for (int j = 0; j < 4; ++j)
        #pragma unroll
        for (int e = 0; e < 4; ++e){
            float2 f = upk(acc[j][e]);
            acc[j][e] = pk(f.x * ivv[e], f.y * ivv[e]);
        }

    // ---- softmax over K=64 per pixel ----
    {
        float pm[4];
        #pragma unroll
        for (int e = 0; e < 4; ++e){
            float m = -3.4e38f;
            #pragma unroll
            for (int j = 0; j < 4; ++j){
                float2 f = upk(acc[j][e]);
                m = fmaxf(m, fmaxf(f.x, f.y));
            }
            pm[e] = m;
        }
        *reinterpret_cast<float4*>(red + kg*256 + nb) = make_float4(pm[0],pm[1],pm[2],pm[3]);
    }
    __syncthreads();
    float M[4];
    {
        float4 m = *reinterpret_cast<const float4*>(red + nb);
        #pragma unroll
        for (int g = 1; g < 8; ++g){
            float4 r = *reinterpret_cast<const float4*>(red + g*256 + nb);
            m.x = fmaxf(m.x, r.x); m.y = fmaxf(m.y, r.y);
            m.z = fmaxf(m.z, r.z); m.w = fmaxf(m.w, r.w);
        }
        M[0]=m.x; M[1]=m.y; M[2]=m.z; M[3]=m.w;
    }
    __syncthreads();
    float ssum[4] = {0.f, 0.f, 0.f, 0.f};
    #pragma unroll
    for (int j = 0; j < 4; ++j)
        #pragma unroll
        for (int e = 0; e < 4; ++e){
            float2 f = upk(acc[j][e]);
            float e0 = __expf(f.x - M[e]);
            float e1 = __expf(f.y - M[e]);
            acc[j][e] = pk(e0, e1);
            ssum[e] += e0 + e1;
        }
    *reinterpret_cast<float4*>(red + kg*256 + nb) = make_float4(ssum[0],ssum[1],ssum[2],ssum[3]);
    __syncthreads();
    float rS[4];
    {
        float4 s = *reinterpret_cast<const float4*>(red + nb);
        #pragma unroll
        for (int g = 1; g < 8; ++g){
            float4 r = *reinterpret_cast<const float4*>(red + g*256 + nb);
            s.x += r.x; s.y += r.y; s.z += r.z; s.w += r.w;
        }
        rS[0]=1.f/s.x; rS[1]=1.f/s.y; rS[2]=1.f/s.z; rS[3]=1.f/s.w;
    }

    // ---- write a' = a*invnorm (float4 rows) + asum partials ----
    const bool valid = (n0 + nb) < N_;     // whole 4-block validity (N_%4==0)
    float* ga = g_a + ((size_t)(b*K_) + kg*8)*NPAD + n0 + nb;
    float ksum[8];
    #pragma unroll
    for (int i = 0; i < 8; ++i) ksum[i] = 0.f;
    #pragma unroll
    for (int j = 0; j < 4; ++j){
        float4 lo4, hi4;
        #pragma unroll
        for (int e = 0; e < 4; ++e){
            float2 f = upk(acc[j][e]);
            float a0 = f.x * rS[e], a1 = f.y * rS[e];
            if (!valid){ a0 = 0.f; a1 = 0.f; }
            ksum[2*j]   += a0;
            ksum[2*j+1] += a1;
            (&lo4.x)[e] = a0 * ivv[e];
            (&hi4.x)[e] = a1 * ivv[e];
        }
        *reinterpret_cast<float4*>(ga + (size_t)(2*j  )*NPAD) = lo4;
        *reinterpret_cast<float4*>(ga + (size_t)(2*j+1)*NPAD) = hi4;
    }
    #pragma unroll
    for (int i = 0; i < 8; ++i){
        float r = ksum[i];
        #pragma unroll
        for (int off = 16; off; off >>= 1) r += __shfl_xor_sync(0xffffffffu, r, off);
        if (ng == 0) wsum[wid*8 + i] = r;
    }
    __syncthreads();
    if (tid < 64)
        g_asum_part[(b*NT_ + tile)*K_ + tid] = wsum[tid] + wsum[64 + tid];
}

// ---------------------------------------------------------------------------
// KB: vlad_raw[b,k,d] = sum_n a'[b,k,n] * x[b,d,n]
//     256 threads, 8 warps, warp = 8k x 128d; thread tile 8k x 4d.
//     a' PLAIN in smem (broadcast LDS.128 -> k-pairs), x LDS.128 + reg dup.
// ---------------------------------------------------------------------------
__global__ __launch_bounds__(256) void kb_vlad(const float* __restrict__ x,
                                               float* __restrict__ out)
{
    __shared__ __align__(16) float xsm[32*132];  // [nn][d], row 528 B
    __shared__ __align__(16) float smA[32*68];   // [nn][k] plain, row 272 B

    const int tid = threadIdx.x;
    const int d0  = blockIdx.x * 128;
    const int b   = blockIdx.y;
    const int kg  = tid >> 5;     // k0 = kg*8
    const int dg  = tid & 31;     // d = 4*dg + e
    const int sl  = tid & 31;     // stager nn
    const int sb  = tid >> 5;     // stager base

    u64 acc[4][4];
    #pragma unroll
    for (int j = 0; j < 4; ++j)
        #pragma unroll
        for (int e = 0; e < 4; ++e) acc[j][e] = 0ULL;

    const float* xb = x   + (size_t)b * D_ * N_;
    const float* ab = g_a + (size_t)b * K_ * NPAD;

    float ra[8], rx[16];
    #pragma unroll
    for (int it = 0; it < 8; ++it)
        ra[it] = ab[(size_t)(sb + 8*it)*NPAD + sl];
    #pragma unroll
    for (int it = 0; it < 16; ++it)
        rx[it] = (sl < N_) ? xb[(size_t)(d0 + sb + 8*it)*N_ + sl] : 0.f;

    for (int n0 = 0; n0 < NPAD; n0 += 32){
        #pragma unroll
        for (int it = 0; it < 8; ++it)
            smA[sl*68 + sb + 8*it] = ra[it];
        #pragma unroll
        for (int it = 0; it < 16; ++it)
            xsm[sl*132 + sb + 8*it] = rx[it];
        __syncthreads();

        if (n0 + 32 < NPAD){
            int gn = n0 + 32 + sl;
            #pragma unroll
            for (int it = 0; it < 8; ++it)
                ra[it] = ab[(size_t)(sb + 8*it)*NPAD + gn];
            #pragma unroll
            for (int it = 0; it < 16; ++it)
                rx[it] = (gn < N_) ? xb[(size_t)(d0 + sb + 8*it)*N_ + gn] : 0.f;
        }

        float4 xf = *reinterpret_cast<const float4*>(xsm + 4*dg);
        ulonglong2 aa = *reinterpret_cast<const ulonglong2*>(smA + kg*8);
        ulonglong2 ab2 = *reinterpret_cast<const ulonglong2*>(smA + kg*8 + 4);
        #pragma unroll
        for (int nn = 0; nn < 32; ++nn){
            float4 xn; ulonglong2 aan, abn;
            if (nn < 31){
                xn  = *reinterpret_cast<const float4*>(xsm + (nn+1)*132 + 4*dg);
                aan = *reinterpret_cast<const ulonglong2*>(smA + (nn+1)*68 + kg*8);
                abn = *reinterpret_cast<const ulonglong2*>(smA + (nn+1)*68 + kg*8 + 4);
            }
            u64 x0 = pk(xf.x, xf.x), x1 = pk(xf.y, xf.y);
            u64 x2 = pk(xf.z, xf.z), x3 = pk(xf.w, xf.w);
            fma2(acc[0][0], aa.x, x0); fma2(acc[0][1], aa.x, x1);
            fma2(acc[0][2], aa.x, x2); fma2(acc[0][3], aa.x, x3);
            fma2(acc[1][0], aa.y, x0); fma2(acc[1][1], aa.y, x1);
            fma2(acc[1][2], aa.y, x2); fma2(acc[1][3], aa.y, x3);
            fma2(acc[2][0], ab2.x, x0); fma2(acc[2][1], ab2.x, x1);
            fma2(acc[2][2], ab2.x, x2); fma2(acc[2][3], ab2.x, x3);
            fma2(acc[3][0], ab2.y, x0); fma2(acc[3][1], ab2.y, x1);
            fma2(acc[3][2], ab2.y, x2); fma2(acc[3][3], ab2.y, x3);
            if (nn < 31){ xf = xn; aa = aan; ab2 = abn; }
        }
        __syncthreads();
    }

    float* ob = out + ((size_t)(b*K_) + kg*8)*D_ + d0 + 4*dg;
    #pragma unroll
    for (int j = 0; j < 4; ++j){
        float4 lo4, hi4;
        #pragma unroll
        for (int e = 0; e < 4; ++e){
            float2 f = upk(acc[j][e]);
            (&lo4.x)[e] = f.x;
            (&hi4.x)[e] = f.y;
        }
        *reinterpret_cast<float4*>(ob + (size_t)(2*j  )*D_) = lo4;
        *reinterpret_cast<float4*>(ob + (size_t)(2*j+1)*D_) = hi4;
    }
}

// ---------------------------------------------------------------------------
// KC: asum from partials, centroid residual, intra-normalize; global L2
//     folded in (rows unit-norm -> global norm = sqrt(64) = 8 -> x0.125).
// ---------------------------------------------------------------------------
__global__ __launch_bounds__(128) void kc_norm(float* __restrict__ out,
                                               const float* __restrict__ cent)
{
    __shared__ float sh[128];
    const int k = blockIdx.x, b = blockIdx.y;
    const int tid = threadIdx.x;

    float s = (tid < NT_) ? g_asum_part[(b*NT_ + tid)*K_ + k] : 0.f;
    sh[tid] = s; __syncthreads();
    for (int o = 64; o; o >>= 1){ if (tid < o) sh[tid] += sh[tid + o]; __syncthreads(); }
    float asum = sh[0];
    __syncthreads();

    float*       row  = out  + ((size_t)(b*K_ + k))*D_;
    const float* crow = cent + (size_t)k*D_;
    float v[4]; float sq = 0.f;
    #pragma unroll
    for (int j = 0; j < 4; ++j){
        int d = tid + 128*j;
        v[j] = row[d] - asum * crow[d];
        sq += v[j]*v[j];
    }
    sh[tid] = sq; __syncthreads();
    for (int o = 64; o; o >>= 1){ if (tid < o) sh[tid] += sh[tid + o]; __syncthreads(); }
    float inv = 0.125f / fmaxf(sqrtf(sh[0]), EPSF);
    #pragma unroll
    for (int j = 0; j < 4; ++j) row[tid + 128*j] = v[j] * inv;
}

// ---------------------------------------------------------------------------
extern "C" void kernel_launch(void* const* d_in, const int* in_sizes, int n_in,
                              void* d_out, int out_size)
{
    const float* x = (const float*)d_in[0];   // (B, D, H, W)
    const float* w = (const float*)d_in[1];   // (K, D)
    const float* c = (const float*)d_in[2];   // (K, D)
    float* out = (float*)d_out;               // (B, K*D)

    ka_logits<<<dim3(NT_, B_), 512>>>(x, w);
    kb_vlad  <<<dim3(D_/128, B_), 256>>>(x, out);
    kc_norm  <<<dim3(K_, B_), 128>>>(out, c);
}

// round 14
// speedup vs baseline: 1.3266x; 1.1758x over previous
#include <cuda_runtime.h>

#define B_    64
#define D_    512
#define N_    1200
#define K_    64
#define NT_   10           // number of 128-wide n tiles
#define NTILE 128
#define NPAD  1280         // NT_*NTILE
#define EPSF  1e-12f

__device__ __align__(16) float g_a[B_ * K_ * NPAD];   // a' = softmax*invnorm, 0-padded
__device__ float g_asum_part[B_ * NT_ * K_];

typedef unsigned long long u64;

static __device__ __forceinline__ u64 pk(float lo, float hi){
    union { u64 u; float2 f; } t; t.f = make_float2(lo, hi); return t.u;
}
static __device__ __forceinline__ float2 upk(u64 v){
    union { u64 u; float2 f; } t; t.u = v; return t.f;
}
static __device__ __forceinline__ void fma2(u64 &acc, u64 a, u64 b){
    asm("fma.rn.f32x2 %0, %1, %2, %0;" : "+l"(acc) : "l"(a), "l"(b));
}

// ---------------------------------------------------------------------------
// KA: logits GEMM (64k x 128n per CTA, D=512) + fused invnorm + softmax.
//     256 threads, 8 warps; warp kg covers k=kg*8..+8 over all 128 n.
//     Thread tile 8k x 4n, k-paired accumulators (R13-validated inner loop:
//     w PLAIN in smem via 2 broadcast LDS.128, x LDS.128 + register dup).
//     launch_bounds(256,2): 2 CTAs/SM -> barrier bubbles covered, and
//     640 CTAs at 2-deep residency cuts the 3-wave tail of R13.
// ---------------------------------------------------------------------------
__global__ __launch_bounds__(256, 2) void ka_logits(const float* __restrict__ x,
                                                    const float* __restrict__ w)
{
    __shared__ __align__(16) float SM[3136];
    float* xs = SM;            // 16 dd x 128 floats (8 KB)
    float* ws = SM + 2048;     // 16 dd x 68 floats (plain w, row 272 B)

    const int tid  = threadIdx.x;
    const int tile = blockIdx.x, b = blockIdx.y;
    const int n0   = tile * NTILE;
    const int wid  = tid >> 5, ng = tid & 31;
    const int kg   = wid;              // k0 = kg*8
    const int nb   = 4*ng;             // 4 pixels nb..nb+3

    u64 acc[4][4];
    #pragma unroll
    for (int j = 0; j < 4; ++j)
        #pragma unroll
        for (int e = 0; e < 4; ++e) acc[j][e] = 0ULL;

    float4 s4 = make_float4(0.f, 0.f, 0.f, 0.f);
    const float* xb = x + (size_t)b * D_ * N_;
    const int n4  = tid & 31;      // x stager column (float4)
    const int rr  = tid >> 5;      // x stager rows rr, rr+8
    const int wdd = tid & 15;      // w stager dd
    const int wk  = tid >> 4;      // w stager k base: k = wk + 16*it
    const int nc  = n0 + 4*n4;
    const bool nvalid = (nc < N_);

    float4 px[2]; float pw[4];
    #pragma unroll
    for (int it = 0; it < 2; ++it){
        px[it] = make_float4(0.f, 0.f, 0.f, 0.f);
        if (nvalid) px[it] = *reinterpret_cast<const float4*>(xb + (size_t)(rr + 8*it)*N_ + nc);
    }
    #pragma unroll
    for (int it = 0; it < 4; ++it) pw[it] = w[(wk + 16*it)*D_ + wdd];

    for (int c = 0; c < D_; c += 16){
        *reinterpret_cast<float4*>(xs + rr*128     + 4*n4) = px[0];
        *reinterpret_cast<float4*>(xs + (rr+8)*128 + 4*n4) = px[1];
        s4.x += px[0].x*px[0].x + px[1].x*px[1].x;
        s4.y += px[0].y*px[0].y + px[1].y*px[1].y;
        s4.z += px[0].z*px[0].z + px[1].z*px[1].z;
        s4.w += px[0].w*px[0].w + px[1].w*px[1].w;
        #pragma unroll
        for (int it = 0; it < 4; ++it) ws[wdd*68 + wk + 16*it] = pw[it];
        __syncthreads();

        if (c + 16 < D_){
            #pragma unroll
            for (int it = 0; it < 2; ++it){
                px[it] = make_float4(0.f, 0.f, 0.f, 0.f);
                if (nvalid) px[it] = *reinterpret_cast<const float4*>(
                                        xb + (size_t)(c + 16 + rr + 8*it)*N_ + nc);
            }
            #pragma unroll
            for (int it = 0; it < 4; ++it) pw[it] = w[(wk + 16*it)*D_ + c + 16 + wdd];
        }

        // pipelined inner loop (R13-validated shape)
        float4 xf = *reinterpret_cast<const float4*>(xs + nb);
        ulonglong2 wa = *reinterpret_cast<const ulonglong2*>(ws + kg*8);
        ulonglong2 wb = *reinterpret_cast<const ulonglong2*>(ws + kg*8 + 4);
        #pragma unroll
        for (int dd = 0; dd < 16; ++dd){
            float4 xn; ulonglong2 wan, wbn;
            if (dd < 15){
                xn  = *reinterpret_cast<const float4*>(xs + (dd+1)*128 + nb);
                wan = *reinterpret_cast<const ulonglong2*>(ws + (dd+1)*68 + kg*8);
                wbn = *reinterpret_cast<const ulonglong2*>(ws + (dd+1)*68 + kg*8 + 4);
            }
            u64 x0 = pk(xf.x, xf.x), x1 = pk(xf.y, xf.y);
            u64 x2 = pk(xf.z, xf.z), x3 = pk(xf.w, xf.w);
            fma2(acc[0][0], wa.x, x0); fma2(acc[0][1], wa.x, x1);
            fma2(acc[0][2], wa.x, x2); fma2(acc[0][3], wa.x, x3);
            fma2(acc[1][0], wa.y, x0); fma2(acc[1][1], wa.y, x1);
            fma2(acc[1][2], wa.y, x2); fma2(acc[1][3], wa.y, x3);
            fma2(acc[2][0], wb.x, x0); fma2(acc[2][1], wb.x, x1);
            fma2(acc[2][2], wb.x, x2); fma2(acc[2][3], wb.x, x3);
            fma2(acc[3][0], wb.y, x0); fma2(acc[3][1], wb.y, x1);
            fma2(acc[3][2], wb.y, x2); fma2(acc[3][3], wb.y, x3);
            if (dd < 15){ xf = xn; wa = wan; wb = wbn; }
        }
        __syncthreads();
    }

    // ---- sumsq -> invnorm ----
    float4* red4 = reinterpret_cast<float4*>(SM);   // 256 float4 = floats [0,1024)
    float*  sinv = SM + 1024;                       // [1024,1152)
    float*  red  = SM + 1152;                       // 8 x 128 floats [1152,2176)
    float*  wsum = SM + 2176;                       // [2176,2240)

    red4[rr*32 + n4] = s4;
    __syncthreads();
    if (tid < 32){
        float sx = 0.f, sy = 0.f, sz = 0.f, sw = 0.f;
        #pragma unroll
        for (int r = 0; r < 8; ++r){
            float4 a0 = red4[r*32 + tid];
            sx += a0.x; sy += a0.y; sz += a0.z; sw += a0.w;
        }
        int nbx = n0 + 4*tid;
        sinv[4*tid+0] = (nbx+0 < N_) ? 1.f/fmaxf(sqrtf(sx), EPSF) : 0.f;
        sinv[4*tid+1] = (nbx+1 < N_) ? 1.f/fmaxf(sqrtf(sy), EPSF) : 0.f;
        sinv[4*tid+2] = (nbx+2 < N_) ? 1.f/fmaxf(sqrtf(sz), EPSF) : 0.f;
        sinv[4*tid+3] = (nbx+3 < N_) ? 1.f/fmaxf(sqrtf(sw), EPSF) : 0.f;
    }
    __syncthreads();

    float ivv[4];
    {
        float4 iv4 = *reinterpret_cast<const float4*>(sinv + nb);
        ivv[0]=iv4.x; ivv[1]=iv4.y; ivv[2]=iv4.z; ivv[3]=iv4.w;
    }
    #pragma unroll
    for (int j = 0; j < 4; ++j)
        #pragma unroll
        for (int e = 0; e < 4; ++e){
            float2 f = upk(acc[j][e]);
            acc[j][e] = pk(f.x * ivv[e], f.y * ivv[e]);
        }

    // ---- softmax over K=64 per pixel ----
    {
        float pm[4];
        #pragma unroll
        for (int e = 0; e < 4; ++e){
            float m = -3.4e38f;
            #pragma unroll
            for (int j = 0; j < 4; ++j){
                float2 f = upk(acc[j][e]);
                m = fmaxf(m, fmaxf(f.x, f.y));
            }
            pm[e] = m;
        }
        *reinterpret_cast<float4*>(red + kg*128 + nb) = make_float4(pm[0],pm[1],pm[2],pm[3]);
    }
    __syncthreads();
    float M[4];
    {
        float4 m = *reinterpret_cast<const float4*>(red + nb);
        #pragma unroll
        for (int g = 1; g < 8; ++g){
            float4 r = *reinterpret_cast<const float4*>(red + g*128 + nb);
            m.x = fmaxf(m.x, r.x); m.y = fmaxf(m.y, r.y);
            m.z = fmaxf(m.z, r.z); m.w = fmaxf(m.w, r.w);
        }
        M[0]=m.x; M[1]=m.y; M[2]=m.z; M[3]=m.w;
    }
    __syncthreads();
    float ssum[4] = {0.f, 0.f, 0.f, 0.f};
    #pragma unroll
    for (int j = 0; j < 4; ++j)
        #pragma unroll
        for (int e = 0; e < 4; ++e){
            float2 f = upk(acc[j][e]);
            float e0 = __expf(f.x - M[e]);
            float e1 = __expf(f.y - M[e]);
            acc[j][e] = pk(e0, e1);
            ssum[e] += e0 + e1;
        }
    *reinterpret_cast<float4*>(red + kg*128 + nb) = make_float4(ssum[0],ssum[1],ssum[2],ssum[3]);
    __syncthreads();
    float rS[4];
    {
        float4 s = *reinterpret_cast<const float4*>(red + nb);
        #pragma unroll
        for (int g = 1; g < 8; ++g){
            float4 r = *reinterpret_cast<const float4*>(red + g*128 + nb);
            s.x += r.x; s.y += r.y; s.z += r.z; s.w += r.w;
        }
        rS[0]=1.f/s.x; rS[1]=1.f/s.y; rS[2]=1.f/s.z; rS[3]=1.f/s.w;
    }

    // ---- write a' = a*invnorm (float4 rows) + asum partials ----
    const bool valid = (n0 + nb) < N_;     // whole 4-block validity (N_%4==0)
    float* ga = g_a + ((size_t)(b*K_) + kg*8)*NPAD + n0 + nb;
    float ksum[8];
    #pragma unroll
    for (int i = 0; i < 8; ++i) ksum[i] = 0.f;
    #pragma unroll
    for (int j = 0; j < 4; ++j){
        float4 lo4, hi4;
        #pragma unroll
        for (int e = 0; e < 4; ++e){
            float2 f = upk(acc[j][e]);
            float a0 = f.x * rS[e], a1 = f.y * rS[e];
            if (!valid){ a0 = 0.f; a1 = 0.f; }
            ksum[2*j]   += a0;
            ksum[2*j+1] += a1;
            (&lo4.x)[e] = a0 * ivv[e];
            (&hi4.x)[e] = a1 * ivv[e];
        }
        *reinterpret_cast<float4*>(ga + (size_t)(2*j  )*NPAD) = lo4;
        *reinterpret_cast<float4*>(ga + (size_t)(2*j+1)*NPAD) = hi4;
    }
    #pragma unroll
    for (int i = 0; i < 8; ++i){
        float r = ksum[i];
        #pragma unroll
        for (int off = 16; off; off >>= 1) r += __shfl_xor_sync(0xffffffffu, r, off);
        if (ng == 0) wsum[kg*8 + i] = r;   // warp covers the full 128-n tile
    }
    __syncthreads();
    if (tid < 64)
        g_asum_part[(b*NT_ + tile)*K_ + tid] = wsum[tid];
}

// ---------------------------------------------------------------------------
// KB: vlad_raw[b,k,d] = sum_n a'[b,k,n] * x[b,d,n]
//     256 threads, 8 warps, warp = 8k x 128d; thread tile 8k x 4d.
//     a' PLAIN in smem (broadcast LDS.128 -> k-pairs), x LDS.128 + reg dup.
//     launch_bounds(256,2): 256 CTAs <= 296 residency slots -> one wave.
// ---------------------------------------------------------------------------
__global__ __launch_bounds__(256, 2) void kb_vlad(const float* __restrict__ x,
                                                  float* __restrict__ out)
{
    __shared__ __align__(16) float xsm[32*132];  // [nn][d], row 528 B
    __shared__ __align__(16) float smA[32*68];   // [nn][k] plain, row 272 B

    const int tid = threadIdx.x;
    const int d0  = blockIdx.x * 128;
    const int b   = blockIdx.y;
    const int kg  = tid >> 5;     // k0 = kg*8
    const int dg  = tid & 31;     // d = 4*dg + e
    const int sl  = tid & 31;     // stager nn
    const int sb  = tid >> 5;     // stager base

    u64 acc[4][4];
    #pragma unroll
    for (int j = 0; j < 4; ++j)
        #pragma unroll
        for (int e = 0; e < 4; ++e) acc[j][e] = 0ULL;

    const float* xb = x   + (size_t)b * D_ * N_;
    const float* ab = g_a + (size_t)b * K_ * NPAD;

    float ra[8], rx[16];
    #pragma unroll
    for (int it = 0; it < 8; ++it)
        ra[it] = ab[(size_t)(sb + 8*it)*NPAD + sl];
    #pragma unroll
    for (int it = 0; it < 16; ++it)
        rx[it] = xb[(size_t)(d0 + sb + 8*it)*N_ + sl];

    for (int n0 = 0; n0 < NPAD; n0 += 32){
        #pragma unroll
        for (int it = 0; it < 8; ++it)
            smA[sl*68 + sb + 8*it] = ra[it];
        #pragma unroll
        for (int it = 0; it < 16; ++it)
            xsm[sl*132 + sb + 8*it] = rx[it];
        __syncthreads();

        if (n0 + 32 < NPAD){
            int gn = n0 + 32 + sl;
            #pragma unroll
            for (int it = 0; it < 8; ++it)
                ra[it] = ab[(size_t)(sb + 8*it)*NPAD + gn];
            #pragma unroll
            for (int it = 0; it < 16; ++it)
                rx[it] = (gn < N_) ? xb[(size_t)(d0 + sb + 8*it)*N_ + gn] : 0.f;
        }

        float4 xf = *reinterpret_cast<const float4*>(xsm + 4*dg);
        ulonglong2 aa  = *reinterpret_cast<const ulonglong2*>(smA + kg*8);
        ulonglong2 ab2 = *reinterpret_cast<const ulonglong2*>(smA + kg*8 + 4);
        #pragma unroll
        for (int nn = 0; nn < 32; ++nn){
            float4 xn; ulonglong2 aan, abn;
            if (nn < 31){
                xn  = *reinterpret_cast<const float4*>(xsm + (nn+1)*132 + 4*dg);
                aan = *reinterpret_cast<const ulonglong2*>(smA + (nn+1)*68 + kg*8);
                abn = *reinterpret_cast<const ulonglong2*>(smA + (nn+1)*68 + kg*8 + 4);
            }
            u64 x0 = pk(xf.x, xf.x), x1 = pk(xf.y, xf.y);
            u64 x2 = pk(xf.z, xf.z), x3 = pk(xf.w, xf.w);
            fma2(acc[0][0], aa.x, x0); fma2(acc[0][1], aa.x, x1);
            fma2(acc[0][2], aa.x, x2); fma2(acc[0][3], aa.x, x3);
            fma2(acc[1][0], aa.y, x0); fma2(acc[1][1], aa.y, x1);
            fma2(acc[1][2], aa.y, x2); fma2(acc[1][3], aa.y, x3);
            fma2(acc[2][0], ab2.x, x0); fma2(acc[2][1], ab2.x, x1);
            fma2(acc[2][2], ab2.x, x2); fma2(acc[2][3], ab2.x, x3);
            fma2(acc[3][0], ab2.y, x0); fma2(acc[3][1], ab2.y, x1);
            fma2(acc[3][2], ab2.y, x2); fma2(acc[3][3], ab2.y, x3);
            if (nn < 31){ xf = xn; aa = aan; ab2 = abn; }
        }
        __syncthreads();
    }

    float* ob = out + ((size_t)(b*K_) + kg*8)*D_ + d0 + 4*dg;
    #pragma unroll
    for (int j = 0; j < 4; ++j){
        float4 lo4, hi4;
        #pragma unroll
        for (int e = 0; e < 4; ++e){
            float2 f = upk(acc[j][e]);
            (&lo4.x)[e] = f.x;
            (&hi4.x)[e] = f.y;
        }
        *reinterpret_cast<float4*>(ob + (size_t)(2*j  )*D_) = lo4;
        *reinterpret_cast<float4*>(ob + (size_t)(2*j+1)*D_) = hi4;
    }
}

// ---------------------------------------------------------------------------
// KC: asum from partials, centroid residual, intra-normalize; global L2
//     folded in (rows unit-norm -> global norm = sqrt(64) = 8 -> x0.125).
// ---------------------------------------------------------------------------
__global__ __launch_bounds__(128) void kc_norm(float* __restrict__ out,
                                               const float* __restrict__ cent)
{
    __shared__ float sh[128];
    const int k = blockIdx.x, b = blockIdx.y;
    const int tid = threadIdx.x;

    float s = (tid < NT_) ? g_asum_part[(b*NT_ + tid)*K_ + k] : 0.f;
    sh[tid] = s; __syncthreads();
    for (int o = 64; o; o >>= 1){ if (tid < o) sh[tid] += sh[tid + o]; __syncthreads(); }
    float asum = sh[0];
    __syncthreads();

    float*       row  = out  + ((size_t)(b*K_ + k))*D_;
    const float* crow = cent + (size_t)k*D_;
    float v[4]; float sq = 0.f;
    #pragma unroll
    for (int j = 0; j < 4; ++j){
        int d = tid + 128*j;
        v[j] = row[d] - asum * crow[d];
        sq += v[j]*v[j];
    }
    sh[tid] = sq; __syncthreads();
    for (int o = 64; o; o >>= 1){ if (tid < o) sh[tid] += sh[tid + o]; __syncthreads(); }
    float inv = 0.125f / fmaxf(sqrtf(sh[0]), EPSF);
    #pragma unroll
    for (int j = 0; j < 4; ++j) row[tid + 128*j] = v[j] * inv;
}

// ---------------------------------------------------------------------------
extern "C" void kernel_launch(void* const* d_in, const int* in_sizes, int n_in,
                              void* d_out, int out_size)
{
    const float* x = (const float*)d_in[0];   // (B, D, H, W)
    const float* w = (const float*)d_in[1];   // (K, D)
    const float* c = (const float*)d_in[2];   // (K, D)
    float* out = (float*)d_out;               // (B, K*D)

    ka_logits<<<dim3(NT_, B_), 256>>>(x, w);
    kb_vlad  <<<dim3(D_/128, B_), 256>>>(x, out);
    kc_norm  <<<dim3(K_, B_), 128>>>(out, c);
}

// round 16
// speedup vs baseline: 2.7404x; 2.0657x over previous
#include <cuda_runtime.h>
#include <cuda_bf16.h>
#include <mma.h>

using namespace nvcuda;

#define B_    64
#define D_    512
#define N_    1200
#define K_    64
#define NT_   10
#define NTILE 128
#define NPAD  1280
#define EPSF  1e-12f

typedef unsigned int u32;

__device__ __align__(16) __nv_bfloat16 g_ab[(size_t)B_ * K_ * NPAD]; // a' bf16, 0-padded
__device__ float g_asum_part[B_ * NT_ * K_];

// ---------------------------------------------------------------------------
// KA: per (b, 128-pixel tile): logits[128n x 64k] = x_raw · W^T via wmma bf16
//     (fp32 accumulate), 8 chunks of 64 d. Sumsq fused into staging; invnorm
//     folded post-GEMM (linearity of the 1x1 conv wrt x). Softmax per pixel,
//     writes a' = a * invnorm (bf16) + per-tile asum partials.
// ---------------------------------------------------------------------------
__global__ __launch_bounds__(256) void ka_logits(const float* __restrict__ x,
                                                 const float* __restrict__ w)
{
    __shared__ __align__(16) char SMU[39936];
    __nv_bfloat16* xbf = reinterpret_cast<__nv_bfloat16*>(SMU);          // [64d][136n]
    __nv_bfloat16* wbf = reinterpret_cast<__nv_bfloat16*>(SMU + 17408);  // [64k][72d]
    float* logit_s = reinterpret_cast<float*>(SMU);                      // [64k][136n] (aliases staging, used post-GEMM)
    float* s_red   = reinterpret_cast<float*>(SMU + 34816);              // [8][128]
    float* s_wsum  = reinterpret_cast<float*>(SMU + 38912);              // [4][64]

    const int tid = threadIdx.x, wid = tid >> 5, lid = tid & 31;
    const int tile = blockIdx.x, b = blockIdx.y;
    const int n0 = tile * NTILE;
    const float* xb = x + (size_t)b * D_ * N_;

    wmma::fragment<wmma::accumulator, 16, 16, 16, float> cfr[4];
    #pragma unroll
    for (int j = 0; j < 4; ++j) wmma::fill_fragment(cfr[j], 0.f);

    const int  nA = n0 + 4*lid;     // float4 column (N_ % 4 == 0)
    const bool vA = nA < N_;
    float4 sq4 = make_float4(0.f, 0.f, 0.f, 0.f);

    for (int ci = 0; ci < 8; ++ci){
        const int c = ci * 64;
        // stage A = x chunk, transposed to [d][n], bf16; fuse sumsq
        #pragma unroll
        for (int i = 0; i < 8; ++i){
            int d = wid + 8*i;
            float4 v = make_float4(0.f, 0.f, 0.f, 0.f);
            if (vA) v = *reinterpret_cast<const float4*>(xb + (size_t)(c + d)*N_ + nA);
            sq4.x += v.x*v.x; sq4.y += v.y*v.y; sq4.z += v.z*v.z; sq4.w += v.w*v.w;
            *reinterpret_cast<__nv_bfloat162*>(xbf + d*136 + 4*lid)     = __floats2bfloat162_rn(v.x, v.y);
            *reinterpret_cast<__nv_bfloat162*>(xbf + d*136 + 4*lid + 2) = __floats2bfloat162_rn(v.z, v.w);
        }
        // stage B = w chunk [k][d], bf16
        #pragma unroll
        for (int i = 0; i < 8; ++i){
            int k = wid + 8*i;
            float2 wv = *reinterpret_cast<const float2*>(w + (size_t)k*D_ + c + 2*lid);
            *reinterpret_cast<__nv_bfloat162*>(wbf + k*72 + 2*lid) = __floats2bfloat162_rn(wv.x, wv.y);
        }
        __syncthreads();
        // warp wid owns n-rows 16*wid..+15, all 64 k
        #pragma unroll
        for (int s = 0; s < 4; ++s){
            wmma::fragment<wmma::matrix_a, 16, 16, 16, __nv_bfloat16, wmma::col_major> af;
            wmma::load_matrix_sync(af, xbf + (16*s)*136 + 16*wid, 136);
            #pragma unroll
            for (int j = 0; j < 4; ++j){
                wmma::fragment<wmma::matrix_b, 16, 16, 16, __nv_bfloat16, wmma::col_major> bf;
                wmma::load_matrix_sync(bf, wbf + (16*j)*72 + 16*s, 72);
                wmma::mma_sync(cfr[j], af, bf, cfr[j]);
            }
        }
        __syncthreads();
    }

    // store logits col-major [k][136n] -> softmax reads are lane-consecutive
    #pragma unroll
    for (int j = 0; j < 4; ++j)
        wmma::store_matrix_sync(logit_s + 16*wid + (16*j)*136, cfr[j], 136, wmma::mem_col_major);
    *reinterpret_cast<float4*>(s_red + wid*128 + 4*lid) = sq4;
    __syncthreads();

    if (tid < 128){
        const int n = tid, gn = n0 + n;
        const bool valid = gn < N_;
        float tot = 0.f;
        #pragma unroll
        for (int ww = 0; ww < 8; ++ww) tot += s_red[ww*128 + n];
        float sinv = valid ? 1.f / fmaxf(sqrtf(tot), EPSF) : 0.f;

        // pass 1: max
        float mx = -3.4e38f;
        #pragma unroll
        for (int k2 = 0; k2 < 64; ++k2)
            mx = fmaxf(mx, logit_s[k2*136 + n] * sinv);
        // pass 2: exp (overwrite in smem), sum
        float se = 0.f;
        #pragma unroll
        for (int k2 = 0; k2 < 64; ++k2){
            float e = __expf(logit_s[k2*136 + n] * sinv - mx);
            logit_s[k2*136 + n] = e;
            se += e;
        }
        const float r  = 1.f / se;
        const float ri = r * sinv;   // 0 for padding pixels -> a' = 0

        __nv_bfloat16* ga = g_ab + (size_t)(b*K_)*NPAD + gn;
        #pragma unroll
        for (int k2 = 0; k2 < 64; ++k2)
            ga[(size_t)k2*NPAD] = __float2bfloat16(logit_s[k2*136 + n] * ri);

        // asum partials: reduce over the 32 pixels of this warp, per k
        #pragma unroll
        for (int k2 = 0; k2 < 64; ++k2){
            float v = valid ? logit_s[k2*136 + n] * r : 0.f;
            #pragma unroll
            for (int off = 16; off; off >>= 1)
                v += __shfl_xor_sync(0xffffffffu, v, off);
            if ((k2 & 31) == lid) s_wsum[wid*64 + k2] = v;
        }
    }
    __syncthreads();
    if (tid < 64)
        g_asum_part[(b*NT_ + tile)*K_ + tid] =
            s_wsum[tid] + s_wsum[64 + tid] + s_wsum[128 + tid] + s_wsum[192 + tid];
}

// ---------------------------------------------------------------------------
// KB: per (b, 128-d tile): vlad_gemm[128d x 64k] = x · a'^T via wmma bf16,
//     19 chunks of 64 n (chunk 19 is all-padding -> skipped). Accumulator
//     fragments stored straight to gmem col-major (ldm = 512).
// ---------------------------------------------------------------------------
__global__ __launch_bounds__(256) void kb_vlad(const float* __restrict__ x,
                                               float* __restrict__ out)
{
    __shared__ __align__(16) char SMU2[27648];
    __nv_bfloat16* xbf = reinterpret_cast<__nv_bfloat16*>(SMU2);          // [128d][72n]
    __nv_bfloat16* abf = reinterpret_cast<__nv_bfloat16*>(SMU2 + 18432);  // [64k][72n]

    const int tid = threadIdx.x, wid = tid >> 5, lid = tid & 31;
    const int d0 = blockIdx.x * 128, b = blockIdx.y;

    wmma::fragment<wmma::accumulator, 16, 16, 16, float> cfr[4];
    #pragma unroll
    for (int j = 0; j < 4; ++j) wmma::fill_fragment(cfr[j], 0.f);

    const float* xb = x + (size_t)b * D_ * N_;
    const char*  ab = reinterpret_cast<const char*>(g_ab + (size_t)(b*K_)*NPAD);

    for (int ci = 0; ci < 19; ++ci){
        const int nc = ci * 64;
        const int gn = nc + 2*lid;
        const bool v = gn < N_;     // gn even, N_ even -> joint validity of the pair
        // stage A = x [d][n] bf16
        #pragma unroll
        for (int i = 0; i < 16; ++i){
            int d = wid + 8*i;
            float2 xv = make_float2(0.f, 0.f);
            if (v) xv = *reinterpret_cast<const float2*>(xb + (size_t)(d0 + d)*N_ + gn);
            *reinterpret_cast<__nv_bfloat162*>(xbf + d*72 + 2*lid) = __floats2bfloat162_rn(xv.x, xv.y);
        }
        // stage B = a' [k][n] bf16 (padding region of g_ab is exact zeros)
        #pragma unroll
        for (int i = 0; i < 8; ++i){
            int k = wid + 8*i;
            u32 av = *reinterpret_cast<const u32*>(ab + ((size_t)k*NPAD + nc)*2 + 4*lid);
            *reinterpret_cast<u32*>(abf + k*72 + 2*lid) = av;
        }
        __syncthreads();
        // warp wid owns d-rows 16*wid..+15, all 64 k
        #pragma unroll
        for (int s = 0; s < 4; ++s){
            wmma::fragment<wmma::matrix_a, 16, 16, 16, __nv_bfloat16, wmma::row_major> af;
            wmma::load_matrix_sync(af, xbf + (16*wid)*72 + 16*s, 72);
            #pragma unroll
            for (int j = 0; j < 4; ++j){
                wmma::fragment<wmma::matrix_b, 16, 16, 16, __nv_bfloat16, wmma::col_major> bf;
                wmma::load_matrix_sync(bf, abf + (16*j)*72 + 16*s, 72);
                wmma::mma_sync(cfr[j], af, bf, cfr[j]);
            }
        }
        __syncthreads();
    }

    // C (d,k): element at out[(b*64 + k)*512 + d0 + d] -> col-major, ldm = D_
    #pragma unroll
    for (int j = 0; j < 4; ++j)
        wmma::store_matrix_sync(out + ((size_t)(b*K_ + 16*j))*D_ + d0 + 16*wid,
                                cfr[j], D_, wmma::mem_col_major);
}

// ---------------------------------------------------------------------------
// KC: asum from partials, centroid residual, intra-normalize; global L2
//     folded in (rows unit-norm -> global norm = sqrt(64) = 8 -> x0.125).
// ---------------------------------------------------------------------------
__global__ __launch_bounds__(128) void kc_norm(float* __restrict__ out,
                                               const float* __restrict__ cent)
{
    __shared__ float sh[128];
    const int k = blockIdx.x, b = blockIdx.y;
    const int tid = threadIdx.x;

    float s = (tid < NT_) ? g_asum_part[(b*NT_ + tid)*K_ + k] : 0.f;
    sh[tid] = s; __syncthreads();
    for (int o = 64; o; o >>= 1){ if (tid < o) sh[tid] += sh[tid + o]; __syncthreads(); }
    float asum = sh[0];
    __syncthreads();

    float*       row  = out  + ((size_t)(b*K_ + k))*D_;
    const float* crow = cent + (size_t)k*D_;
    float v[4]; float sq = 0.f;
    #pragma unroll
    for (int j = 0; j < 4; ++j){
        int d = tid + 128*j;
        v[j] = row[d] - asum * crow[d];
        sq += v[j]*v[j];
    }
    sh[tid] = sq; __syncthreads();
    for (int o = 64; o; o >>= 1){ if (tid < o) sh[tid] += sh[tid + o]; __syncthreads(); }
    float inv = 0.125f / fmaxf(sqrtf(sh[0]), EPSF);
    #pragma unroll
    for (int j = 0; j < 4; ++j) row[tid + 128*j] = v[j] * inv;
}

// ---------------------------------------------------------------------------
extern "C" void kernel_launch(void* const* d_in, const int* in_sizes, int n_in,
                              void* d_out, int out_size)
{
    const float* x = (const float*)d_in[0];   // (B, D, H, W)
    const float* w = (const float*)d_in[1];   // (K, D)
    const float* c = (const float*)d_in[2];   // (K, D)
    float* out = (float*)d_out;               // (B, K*D)

    ka_logits<<<dim3(NT_, B_), 256>>>(x, w);
    kb_vlad  <<<dim3(D_/128, B_), 256>>>(x, out);
    kc_norm  <<<dim3(K_, B_), 128>>>(out, c);
}